// round 15
// baseline (speedup 1.0000x reference)
#include <cuda_runtime.h>
#include <cuda_fp16.h>

#define NN 25000
#define EE 100000
#define NH 4
#define CC 280
#define HC 1120

// ---------------- scratch ----------------
__device__ __align__(16) float g_M[NH * 256];
__device__ __align__(16) float g_G[NH * 6 * 16];
__device__ __align__(16) float g_g0[NH * 6];
__device__ __align__(16) float g_u[NH * 16];
__device__ __align__(16) float g_w[NH * 16];
__device__ __align__(16) float g_c0[NH];

__device__ __align__(16) float g_p[NN * 64];     // x_i @ M_h  [N][H][16]
__device__ __align__(16) float g_xgp[NN * 32];   // [N][H][8] (6 used)
__device__ __align__(16) float g_sd[NN * 4];
__device__ __align__(16) float g_ss[NN * 4];

__device__ __align__(16) __half2 g_Th[NN * 32];  // sum ex*x[src], f16x2: [N][H][8 half2]
__device__ __align__(16) float g_Sp[NN * 32];    // [N][H][8]: S[0..5], A at [6]

__device__ __align__(16) float g_Wc[112 * 64];   // combined (W108 @ W1)
__device__ __align__(16) float g_bc[64];         // b1 + bskip @ W1

__device__ __forceinline__ float wsum(float s) {
    s += __shfl_xor_sync(0xffffffffu, s, 16);
    s += __shfl_xor_sync(0xffffffffu, s, 8);
    s += __shfl_xor_sync(0xffffffffu, s, 4);
    s += __shfl_xor_sync(0xffffffffu, s, 2);
    s += __shfl_xor_sync(0xffffffffu, s, 1);
    return s;
}

__device__ __forceinline__ void red4(float* p, float a, float b, float c, float d) {
    asm volatile("red.global.add.v4.f32 [%0], {%1,%2,%3,%4};"
                 :: "l"(__cvta_generic_to_global(p)), "f"(a), "f"(b), "f"(c), "f"(d) : "memory");
}
__device__ __forceinline__ void red2(float* p, float a, float b) {
    asm volatile("red.global.add.v2.f32 [%0], {%1,%2};"
                 :: "l"(__cvta_generic_to_global(p)), "f"(a), "f"(b) : "memory");
}
__device__ __forceinline__ void red1(float* p, float a) {
    asm volatile("red.global.add.f32 [%0], %1;"
                 :: "l"(__cvta_generic_to_global(p)), "f"(a) : "memory");
}
__device__ __forceinline__ void redh2(__half2* p, __half2 v) {
    unsigned int u = *(unsigned int*)&v;
    asm volatile("red.global.add.noftz.f16x2 [%0], %1;"
                 :: "l"(__cvta_generic_to_global(p)), "r"(u) : "memory");
}
// packed f32x2 ops (sm_103a, PTX-only)
__device__ __forceinline__ void ffma2(unsigned long long& acc, unsigned long long a, unsigned long long b) {
    asm("fma.rn.f32x2 %0, %1, %2, %0;" : "+l"(acc) : "l"(a), "l"(b));
}
__device__ __forceinline__ unsigned long long dup2(float v) {
    unsigned long long r;
    asm("mov.b64 %0, {%1, %1};" : "=l"(r) : "f"(v));
    return r;
}
__device__ __forceinline__ unsigned long long pack2(float lo, float hi) {
    unsigned long long r;
    asm("mov.b64 %0, {%1, %2};" : "=l"(r) : "f"(lo), "f"(hi));
    return r;
}
__device__ __forceinline__ void unpack2(unsigned long long v, float& lo, float& hi) {
    asm("mov.b64 {%0, %1}, %2;" : "=f"(lo), "=f"(hi) : "l"(v));
}

// ---------------- kA: fused tiny contractions + combined MLP weight ----------------
__global__ __launch_bounds__(256) void kA(const float* __restrict__ Wq, const float* __restrict__ bq,
                                          const float* __restrict__ Wk, const float* __restrict__ bk,
                                          const float* __restrict__ We, const float* __restrict__ Wv,
                                          const float* __restrict__ bv, const float* __restrict__ Wskip,
                                          const float* __restrict__ W1, const float* __restrict__ b1,
                                          const float* __restrict__ bskip) {
    if (blockIdx.x < 196) {
        int g = blockIdx.x * 8 + (threadIdx.x >> 5);
        int lane = threadIdx.x & 31;
        if (g >= 1564) return;
        const float *pa, *pb;
        float* op;
        if (g < 1024) {
            int h = g >> 8, a = (g >> 4) & 15, b = g & 15;
            pa = Wq + a * HC + h * CC; pb = Wk + b * HC + h * CC; op = &g_M[g];
        } else if (g < 1408) {
            int t = g - 1024, h = t / 96, r = t % 96, dd = r >> 4, a = r & 15;
            pa = Wq + a * HC + h * CC; pb = We + dd * HC + h * CC; op = &g_G[(h * 6 + dd) * 16 + a];
        } else if (g < 1472) {
            int t = g - 1408, h = t >> 4, a = t & 15;
            pa = Wq + a * HC + h * CC; pb = bk + h * CC; op = &g_u[t];
        } else if (g < 1536) {
            int t = g - 1472, h = t >> 4, a = t & 15;
            pa = Wk + a * HC + h * CC; pb = bq + h * CC; op = &g_w[t];
        } else if (g < 1540) {
            int h = g - 1536;
            pa = bq + h * CC; pb = bk + h * CC; op = &g_c0[h];
        } else {
            int t = g - 1540, h = t / 6, dd = t - h * 6;
            pa = bq + h * CC; pb = We + dd * HC + h * CC; op = &g_g0[t];
        }
        float s = 0.f;
        for (int c = lane; c < CC; c += 32) s += pa[c] * pb[c];
        s = wsum(s);
        if (lane == 0) *op = s;
    } else {
        int idx = (blockIdx.x - 196) * 256 + threadIdx.x;
        if (idx < 7168) {
            int j = idx >> 6, c = idx & 63;
            float s = 0.f;
            if (j < 108) {
                const float* src;
                float sc = 0.25f;
                if (j < 64)      { int h = j >> 4, a = j & 15; src = Wv + a * HC + h * CC; }
                else if (j < 88) { int t = j - 64, h = t / 6, dd = t - h * 6; src = We + dd * HC + h * CC; }
                else if (j < 104){ src = Wskip + (j - 88) * CC; sc = 1.f; }
                else             { int h = j - 104; src = bv + h * CC; }
                float s0 = 0.f, s1 = 0.f, s2 = 0.f, s3 = 0.f;
                for (int k = 0; k + 4 <= CC; k += 4) {
                    s0 += src[k]     * W1[(k)     * 64 + c];
                    s1 += src[k + 1] * W1[(k + 1) * 64 + c];
                    s2 += src[k + 2] * W1[(k + 2) * 64 + c];
                    s3 += src[k + 3] * W1[(k + 3) * 64 + c];
                }
                s = ((s0 + s1) + (s2 + s3)) * sc;
            }
            g_Wc[idx] = s;
        } else if (idx < 7232) {
            int c = idx - 7168;
            float s0 = 0.f, s1 = 0.f;
            for (int k = 0; k + 2 <= CC; k += 2) {
                s0 += bskip[k]     * W1[(k)     * 64 + c];
                s1 += bskip[k + 1] * W1[(k + 1) * 64 + c];
            }
            g_bc[c] = s0 + s1 + b1[c];
        }
    }
}

// ---------------- K1: per-(node,head) precompute + zero accumulators (PDL consumer) ------
__global__ __launch_bounds__(256) void k1(const float* __restrict__ x) {
    __shared__ float sM[NH * 256];
    __shared__ float sG[NH * 96];
    __shared__ float sU[NH * 16];
    __shared__ float sW[NH * 16];
    __shared__ float sC0[NH];
    __shared__ float sG0[NH * 6];

    // --- prefix: load x (harness input, no dependency on kA) ---
    int gid = blockIdx.x * 256 + threadIdx.x;
    int i = gid >> 2, h = gid & 3;
    float xv[16];
    bool act = (i < NN);
    if (act) {
        const float4* xr = (const float4*)(x + (size_t)i * 16);
#pragma unroll
        for (int t = 0; t < 4; t++) {
            float4 f = xr[t];
            xv[4 * t + 0] = f.x; xv[4 * t + 1] = f.y; xv[4 * t + 2] = f.z; xv[4 * t + 3] = f.w;
        }
    }

    cudaGridDependencySynchronize();   // kA results now visible

    for (int t = threadIdx.x; t < NH * 256; t += 256) sM[t] = g_M[t];
    if (threadIdx.x < NH * 96) sG[threadIdx.x] = g_G[threadIdx.x];
    if (threadIdx.x < NH * 16) { sU[threadIdx.x] = g_u[threadIdx.x]; sW[threadIdx.x] = g_w[threadIdx.x]; }
    if (threadIdx.x < NH) sC0[threadIdx.x] = g_c0[threadIdx.x];
    if (threadIdx.x < NH * 6) sG0[threadIdx.x] = g_g0[threadIdx.x];
    __syncthreads();

    if (!act) return;
    const float4 z4 = make_float4(0.f, 0.f, 0.f, 0.f);
    float4* po = (float4*)(g_p + i * 64 + h * 16);
#pragma unroll
    for (int t = 0; t < 4; t++) {
        float pv[4];
#pragma unroll
        for (int j = 0; j < 4; j++) {
            int b = t * 4 + j;
            float s = 0.f;
#pragma unroll
            for (int a = 0; a < 16; a++) s += xv[a] * sM[(h * 16 + a) * 16 + b];
            pv[j] = s;
        }
        po[t] = make_float4(pv[0], pv[1], pv[2], pv[3]);
    }
    // zero f16x2 T accumulators (32B per (i,h))
    float4* tz = (float4*)(g_Th + i * 32 + h * 8);
    tz[0] = z4; tz[1] = z4;

    float xg[6];
#pragma unroll
    for (int dd = 0; dd < 6; dd++) {
        float s = sG0[h * 6 + dd];
#pragma unroll
        for (int a = 0; a < 16; a++) s += xv[a] * sG[(h * 6 + dd) * 16 + a];
        xg[dd] = s;
    }
    float4* xo = (float4*)(g_xgp + i * 32 + h * 8);
    xo[0] = make_float4(xg[0], xg[1], xg[2], xg[3]);
    *(float2*)(g_xgp + i * 32 + h * 8 + 4) = make_float2(xg[4], xg[5]);
    float4* so = (float4*)(g_Sp + i * 32 + h * 8);
    so[0] = z4; so[1] = z4;   // zeros S[0..5] and A slot [6]

    float su = sC0[h], sw = 0.f;
#pragma unroll
    for (int a = 0; a < 16; a++) {
        su += xv[a] * sU[h * 16 + a];
        sw += xv[a] * sW[h * 16 + a];
    }
    g_sd[i * 4 + h] = su;
    g_ss[i * 4 + h] = sw;
}

// ---------------- K2: edge pass (PDL consumer), T reds in f16x2 ----------------
__global__ __launch_bounds__(256) void k2(const int* __restrict__ ei,
                                          const float* __restrict__ x,
                                          const float* __restrict__ ea) {
    int gid = blockIdx.x * 256 + threadIdx.x;
    bool act = (gid < EE * 4);
    int e = gid >> 2, h = gid & 3;
    int s = 0, d = 0;
    float xs[16], eav[6];
    if (act) {
        s = __ldg(ei + e);
        d = __ldg(ei + EE + e);
        const float4* xr = (const float4*)(x + (size_t)s * 16);
#pragma unroll
        for (int t = 0; t < 4; t++) {
            float4 f = __ldg(xr + t);
            xs[4 * t + 0] = f.x; xs[4 * t + 1] = f.y; xs[4 * t + 2] = f.z; xs[4 * t + 3] = f.w;
        }
        const float2* er = (const float2*)(ea + (size_t)e * 6);
#pragma unroll
        for (int t = 0; t < 3; t++) {
            float2 f = __ldg(er + t);
            eav[2 * t] = f.x; eav[2 * t + 1] = f.y;
        }
    }

    cudaGridDependencySynchronize();   // k1 results now visible
    if (!act) return;

    float al = __ldg(g_sd + d * 4 + h) + __ldg(g_ss + s * 4 + h);
    const float4* pd = (const float4*)(g_p + d * 64 + h * 16);
#pragma unroll
    for (int t = 0; t < 4; t++) {
        float4 f = __ldg(pd + t);
        al += f.x * xs[4 * t + 0] + f.y * xs[4 * t + 1] + f.z * xs[4 * t + 2] + f.w * xs[4 * t + 3];
    }
    float4 xga = __ldg((const float4*)(g_xgp + d * 32 + h * 8));
    float2 xgb = __ldg((const float2*)(g_xgp + d * 32 + h * 8 + 4));
    al += eav[0] * xga.x + eav[1] * xga.y + eav[2] * xga.z + eav[3] * xga.w
        + eav[4] * xgb.x + eav[5] * xgb.y;
    al *= 0.05976143046671968f;  // 1/sqrt(280)
    float ex = __expf(al);

    float* Sd = g_Sp + d * 32 + h * 8;
    red4(Sd, ex * eav[0], ex * eav[1], ex * eav[2], ex * eav[3]);
    red2(Sd + 4, ex * eav[4], ex * eav[5]);
    red1(Sd + 6, ex);
    __half2* Td = g_Th + d * 32 + h * 8;
#pragma unroll
    for (int j = 0; j < 8; j++)
        redh2(Td + j, __floats2half2_rn(ex * xs[2 * j], ex * xs[2 * j + 1]));
}

// ---------------- K6: fused MLP (R12 proven; T staged from f16x2) ----------
#define FP 68
#define K6DYN ((7168 + 112 * FP) * 4)
__global__ __launch_bounds__(256) void k6(const float* __restrict__ x,
                                          const float* __restrict__ W2,
                                          const float* __restrict__ b2,
                                          const float* __restrict__ W3,
                                          const float* __restrict__ b3,
                                          float* __restrict__ out) {
    extern __shared__ float dyn[];
    float* Wcs = dyn;              // [112][64]
    float* Fs = dyn + 7168;        // [112][FP]
    float* Hs1 = dyn;              // alias of Wcs after stage 1: [64][68]
    __shared__ float invAs[256], als[256];
    __shared__ float W2s[1024], b2s[16], W3s[96], b3s[6], bcs[64];

    int tid = threadIdx.x;
    int nodeBase = blockIdx.x * 64;

    // --- prefix: harness inputs only ---
    for (int t = tid; t < 1024; t += 256) W2s[t] = W2[t];
    if (tid < 16) b2s[tid] = b2[tid];
    if (tid < 96) W3s[tid] = W3[tid];
    if (tid < 6) b3s[tid] = b3[tid];

    cudaGridDependencySynchronize();   // k2 (and transitively kA/k1) complete

    for (int t = tid; t < 7168; t += 256) Wcs[t] = g_Wc[t];
    if (tid < 64) bcs[tid] = g_bc[tid];
    {
        int n = tid >> 2;
        int node = nodeBase + n;
        float a = (node < NN) ? g_Sp[node * 32 + (tid & 3) * 8 + 6] : 0.f;
        float inv = 1.f / (a + 1e-16f);
        invAs[tid] = inv;
        als[tid] = a * inv;
    }
    __syncthreads();

    // T: 64 nodes x 4 heads x 2 uint4-chunks (each = 4 half2 = 8 values)
    for (int idx = tid; idx < 512; idx += 256) {
        int n = idx >> 3, r = idx & 7;
        int h = r >> 1, g = r & 1;
        int node = nodeBase + n;
        uint4 raw = make_uint4(0u, 0u, 0u, 0u);
        if (node < NN) raw = *(const uint4*)(g_Th + node * 32 + h * 8 + g * 4);
        float inv = invAs[n * 4 + h];
        const __half2* hp = (const __half2*)&raw;
        int rowBase = h * 16 + g * 8;
#pragma unroll
        for (int j = 0; j < 4; j++) {
            float2 f = __half22float2(hp[j]);
            Fs[(rowBase + 2 * j) * FP + n]     = f.x * inv;
            Fs[(rowBase + 2 * j + 1) * FP + n] = f.y * inv;
        }
    }
    for (int idx = tid; idx < 2048; idx += 256) {          // S: 64 nodes x 24 (of 32)
        int n = idx >> 5, r = idx & 31;
        if (r < 24) {
            int node = nodeBase + n;
            int h = r / 6, dd = r - h * 6;
            float v = (node < NN) ? g_Sp[node * 32 + h * 8 + dd] * invAs[n * 4 + h] : 0.f;
            Fs[(64 + r) * FP + n] = v;
        }
    }
    for (int idx = tid; idx < 1024; idx += 256) {          // x: 64 nodes x 16
        int n = idx >> 4, f = idx & 15;
        int node = nodeBase + n;
        Fs[(88 + f) * FP + n] = (node < NN) ? x[(size_t)node * 16 + f] : 0.f;
    }
    {
        int n = tid >> 2, h = tid & 3;
        Fs[(104 + h) * FP + n] = als[tid];
        Fs[(108 + h) * FP + n] = 0.f;
    }
    __syncthreads();

    // stage 1: [64 nodes] x [64 cols], K=112, 4x4 FFMA2 tile, 2-deep pipeline
    int tx = tid & 15, ty = tid >> 4;
    unsigned long long a2[2][4] = {{0ull, 0ull, 0ull, 0ull}, {0ull, 0ull, 0ull, 0ull}};
    const float* fbase = Fs + ty * 4;
    const float* wbase = Wcs + tx * 4;
    ulonglong2 fp_n = *(const ulonglong2*)(fbase);
    float4 wv_n = *(const float4*)(wbase);
#pragma unroll 4
    for (int k = 0; k < 112; k++) {
        ulonglong2 fp = fp_n;
        float4 wv = wv_n;
        if (k < 111) {
            fp_n = *(const ulonglong2*)(fbase + (k + 1) * FP);
            wv_n = *(const float4*)(wbase + (k + 1) * 64);
        }
        unsigned long long w0 = dup2(wv.x), w1 = dup2(wv.y), w2 = dup2(wv.z), w3 = dup2(wv.w);
        ffma2(a2[0][0], fp.x, w0); ffma2(a2[0][1], fp.x, w1);
        ffma2(a2[0][2], fp.x, w2); ffma2(a2[0][3], fp.x, w3);
        ffma2(a2[1][0], fp.y, w0); ffma2(a2[1][1], fp.y, w1);
        ffma2(a2[1][2], fp.y, w2); ffma2(a2[1][3], fp.y, w3);
    }
    __syncthreads();  // done reading Wcs; safe to alias as Hs1
#pragma unroll
    for (int p = 0; p < 2; p++)
#pragma unroll
        for (int j = 0; j < 4; j++) {
            float lo, hi;
            unpack2(a2[p][j], lo, hi);
            float b = bcs[tx * 4 + j];
            Hs1[(ty * 4 + 2 * p) * 68 + tx * 4 + j]     = fmaxf(lo + b, 0.f);
            Hs1[(ty * 4 + 2 * p + 1) * 68 + tx * 4 + j] = fmaxf(hi + b, 0.f);
        }
    __syncthreads();

    // stage 2+3: 4 lanes per node, packed FFMA2
    int n = tid >> 2, q = tid & 3;
    int node = nodeBase + n;
    unsigned long long h2p[2];
    h2p[0] = pack2(b2s[q * 4 + 0], b2s[q * 4 + 1]);
    h2p[1] = pack2(b2s[q * 4 + 2], b2s[q * 4 + 3]);
#pragma unroll 8
    for (int k = 0; k < 64; k++) {
        unsigned long long hd = dup2(Hs1[n * 68 + k]);
        ulonglong2 wp = *(const ulonglong2*)(W2s + k * 16 + q * 4);
        ffma2(h2p[0], hd, wp.x);
        ffma2(h2p[1], hd, wp.y);
    }
    float h2[4];
    unpack2(h2p[0], h2[0], h2[1]);
    unpack2(h2p[1], h2[2], h2[3]);
#pragma unroll
    for (int mm = 0; mm < 4; mm++) h2[mm] = fmaxf(h2[mm], 0.f);

    float lg[6];
#pragma unroll
    for (int o = 0; o < 6; o++) {
        float pz = 0.f;
#pragma unroll
        for (int mm = 0; mm < 4; mm++) pz += h2[mm] * W3s[(q * 4 + mm) * 6 + o];
        lg[o] = pz;
    }
#pragma unroll
    for (int o = 0; o < 6; o++) {
        lg[o] += __shfl_xor_sync(0xffffffffu, lg[o], 1);
        lg[o] += __shfl_xor_sync(0xffffffffu, lg[o], 2);
        lg[o] += b3s[o];
    }
    float mx = lg[0];
#pragma unroll
    for (int o = 1; o < 6; o++) mx = fmaxf(mx, lg[o]);
    float ev[6], sum = 0.f;
#pragma unroll
    for (int o = 0; o < 6; o++) { ev[o] = __expf(lg[o] - mx); sum += ev[o]; }
    float inv = 1.f / sum;
    if (q == 0 && node < NN) {
#pragma unroll
        for (int o = 0; o < 6; o++) out[node * 6 + o] = ev[o] * inv;
    }
}

// ---------------- launch (PDL chaining) ----------------
template <typename... Args>
static void launch_pdl(void (*kern)(Args...), dim3 grid, dim3 block, size_t smem, Args... args) {
    cudaLaunchConfig_t cfg = {};
    cfg.gridDim = grid;
    cfg.blockDim = block;
    cfg.dynamicSmemBytes = smem;
    cfg.stream = 0;
    cudaLaunchAttribute attr[1];
    attr[0].id = cudaLaunchAttributeProgrammaticStreamSerialization;
    attr[0].val.programmaticStreamSerializationAllowed = 1;
    cfg.attrs = attr;
    cfg.numAttrs = 1;
    cudaLaunchKernelEx(&cfg, kern, args...);
}

extern "C" void kernel_launch(void* const* d_in, const int* in_sizes, int n_in,
                              void* d_out, int out_size) {
    const float* x      = (const float*)d_in[0];
    const int* ei       = (const int*)d_in[1];
    const float* ea     = (const float*)d_in[2];
    const float* Wq     = (const float*)d_in[3];
    const float* bq     = (const float*)d_in[4];
    const float* Wk     = (const float*)d_in[5];
    const float* bk     = (const float*)d_in[6];
    const float* Wv     = (const float*)d_in[7];
    const float* bv     = (const float*)d_in[8];
    const float* We     = (const float*)d_in[9];
    const float* Wskip  = (const float*)d_in[10];
    const float* bskip  = (const float*)d_in[11];
    const float* W1     = (const float*)d_in[12];
    const float* b1     = (const float*)d_in[13];
    const float* W2     = (const float*)d_in[14];
    const float* b2     = (const float*)d_in[15];
    const float* W3     = (const float*)d_in[16];
    const float* b3     = (const float*)d_in[17];
    float* out = (float*)d_out;

    cudaFuncSetAttribute(k6, cudaFuncAttributeMaxDynamicSharedMemorySize, K6DYN);

    kA<<<226, 256>>>(Wq, bq, Wk, bk, We, Wv, bv, Wskip, W1, b1, bskip);
    launch_pdl(k1, dim3(391), dim3(256), (size_t)0, x);
    launch_pdl(k2, dim3(1563), dim3(256), (size_t)0, ei, x, ea);
    launch_pdl(k6, dim3(391), dim3(256), (size_t)K6DYN, x, W2, b2, W3, b3, out);
}

// round 16
// speedup vs baseline: 1.0844x; 1.0844x over previous
#include <cuda_runtime.h>

#define NN 25000
#define EE 100000
#define NH 4
#define CC 280
#define HC 1120

// ---------------- scratch ----------------
__device__ __align__(16) float g_M[NH * 256];
__device__ __align__(16) float g_G[NH * 6 * 16];
__device__ __align__(16) float g_g0[NH * 6];
__device__ __align__(16) float g_u[NH * 16];
__device__ __align__(16) float g_w[NH * 16];
__device__ __align__(16) float g_c0[NH];

__device__ __align__(16) float g_p[NN * 64];     // x_i @ M_h  [N][H][16]
__device__ __align__(16) float g_xgp[NN * 32];   // [N][H][8] (6 used)
__device__ __align__(16) float g_sd[NN * 4];
__device__ __align__(16) float g_ss[NN * 4];

__device__ __align__(16) float g_T[NN * 64];     // sum ex*x[src]  [N][H][16]
__device__ __align__(16) float g_Sp[NN * 32];    // [N][H][8]: S[0..5], A at [6]

__device__ __align__(16) float g_Wc[112 * 64];   // combined (W108 @ W1)
__device__ __align__(16) float g_bc[64];         // b1 + bskip @ W1

__device__ __forceinline__ float wsum(float s) {
    s += __shfl_xor_sync(0xffffffffu, s, 16);
    s += __shfl_xor_sync(0xffffffffu, s, 8);
    s += __shfl_xor_sync(0xffffffffu, s, 4);
    s += __shfl_xor_sync(0xffffffffu, s, 2);
    s += __shfl_xor_sync(0xffffffffu, s, 1);
    return s;
}

__device__ __forceinline__ void red4(float* p, float a, float b, float c, float d) {
    asm volatile("red.global.add.v4.f32 [%0], {%1,%2,%3,%4};"
                 :: "l"(__cvta_generic_to_global(p)), "f"(a), "f"(b), "f"(c), "f"(d) : "memory");
}
// packed f32x2 ops (sm_103a, PTX-only)
__device__ __forceinline__ void ffma2(unsigned long long& acc, unsigned long long a, unsigned long long b) {
    asm("fma.rn.f32x2 %0, %1, %2, %0;" : "+l"(acc) : "l"(a), "l"(b));
}
__device__ __forceinline__ unsigned long long dup2(float v) {
    unsigned long long r;
    asm("mov.b64 %0, {%1, %1};" : "=l"(r) : "f"(v));
    return r;
}
__device__ __forceinline__ unsigned long long pack2(float lo, float hi) {
    unsigned long long r;
    asm("mov.b64 %0, {%1, %2};" : "=l"(r) : "f"(lo), "f"(hi));
    return r;
}
__device__ __forceinline__ void unpack2(unsigned long long v, float& lo, float& hi) {
    asm("mov.b64 {%0, %1}, %2;" : "=f"(lo), "=f"(hi) : "l"(v));
}

// ---------------- kA: tiny weight contractions only (196 blocks) ----------------
__global__ __launch_bounds__(256) void kA(const float* __restrict__ Wq, const float* __restrict__ bq,
                                          const float* __restrict__ Wk, const float* __restrict__ bk,
                                          const float* __restrict__ We) {
    int g = blockIdx.x * 8 + (threadIdx.x >> 5);
    int lane = threadIdx.x & 31;
    if (g >= 1564) return;
    const float *pa, *pb;
    float* op;
    if (g < 1024) {
        int h = g >> 8, a = (g >> 4) & 15, b = g & 15;
        pa = Wq + a * HC + h * CC; pb = Wk + b * HC + h * CC; op = &g_M[g];
    } else if (g < 1408) {
        int t = g - 1024, h = t / 96, r = t % 96, dd = r >> 4, a = r & 15;
        pa = Wq + a * HC + h * CC; pb = We + dd * HC + h * CC; op = &g_G[(h * 6 + dd) * 16 + a];
    } else if (g < 1472) {
        int t = g - 1408, h = t >> 4, a = t & 15;
        pa = Wq + a * HC + h * CC; pb = bk + h * CC; op = &g_u[t];
    } else if (g < 1536) {
        int t = g - 1472, h = t >> 4, a = t & 15;
        pa = Wk + a * HC + h * CC; pb = bq + h * CC; op = &g_w[t];
    } else if (g < 1540) {
        int h = g - 1536;
        pa = bq + h * CC; pb = bk + h * CC; op = &g_c0[h];
    } else {
        int t = g - 1540, h = t / 6, dd = t - h * 6;
        pa = bq + h * CC; pb = We + dd * HC + h * CC; op = &g_g0[t];
    }
    float s = 0.f;
    for (int c = lane; c < CC; c += 32) s += pa[c] * pb[c];
    s = wsum(s);
    if (lane == 0) *op = s;
}

// ---------------- K1: per-(node,head) precompute + zero accumulators (PDL consumer) ------
__global__ __launch_bounds__(256) void k1(const float* __restrict__ x) {
    __shared__ float sM[NH * 256];
    __shared__ float sG[NH * 96];
    __shared__ float sU[NH * 16];
    __shared__ float sW[NH * 16];
    __shared__ float sC0[NH];
    __shared__ float sG0[NH * 6];

    // --- prefix: load x (harness input, no dependency on kA) ---
    int gid = blockIdx.x * 256 + threadIdx.x;
    int i = gid >> 2, h = gid & 3;
    float xv[16];
    bool act = (i < NN);
    if (act) {
        const float4* xr = (const float4*)(x + (size_t)i * 16);
#pragma unroll
        for (int t = 0; t < 4; t++) {
            float4 f = xr[t];
            xv[4 * t + 0] = f.x; xv[4 * t + 1] = f.y; xv[4 * t + 2] = f.z; xv[4 * t + 3] = f.w;
        }
    }

    cudaGridDependencySynchronize();   // kA results now visible

    for (int t = threadIdx.x; t < NH * 256; t += 256) sM[t] = g_M[t];
    if (threadIdx.x < NH * 96) sG[threadIdx.x] = g_G[threadIdx.x];
    if (threadIdx.x < NH * 16) { sU[threadIdx.x] = g_u[threadIdx.x]; sW[threadIdx.x] = g_w[threadIdx.x]; }
    if (threadIdx.x < NH) sC0[threadIdx.x] = g_c0[threadIdx.x];
    if (threadIdx.x < NH * 6) sG0[threadIdx.x] = g_g0[threadIdx.x];
    __syncthreads();

    if (!act) return;
    const float4 z4 = make_float4(0.f, 0.f, 0.f, 0.f);
    float4* po = (float4*)(g_p + i * 64 + h * 16);
    float4* to = (float4*)(g_T + i * 64 + h * 16);
#pragma unroll
    for (int t = 0; t < 4; t++) {
        float pv[4];
#pragma unroll
        for (int j = 0; j < 4; j++) {
            int b = t * 4 + j;
            float s = 0.f;
#pragma unroll
            for (int a = 0; a < 16; a++) s += xv[a] * sM[(h * 16 + a) * 16 + b];
            pv[j] = s;
        }
        po[t] = make_float4(pv[0], pv[1], pv[2], pv[3]);
        to[t] = z4;
    }
    float xg[6];
#pragma unroll
    for (int dd = 0; dd < 6; dd++) {
        float s = sG0[h * 6 + dd];
#pragma unroll
        for (int a = 0; a < 16; a++) s += xv[a] * sG[(h * 6 + dd) * 16 + a];
        xg[dd] = s;
    }
    float4* xo = (float4*)(g_xgp + i * 32 + h * 8);
    xo[0] = make_float4(xg[0], xg[1], xg[2], xg[3]);
    *(float2*)(g_xgp + i * 32 + h * 8 + 4) = make_float2(xg[4], xg[5]);
    float4* so = (float4*)(g_Sp + i * 32 + h * 8);
    so[0] = z4; so[1] = z4;   // zeros S[0..5] and A slot [6]

    float su = sC0[h], sw = 0.f;
#pragma unroll
    for (int a = 0; a < 16; a++) {
        su += xv[a] * sU[h * 16 + a];
        sw += xv[a] * sW[h * 16 + a];
    }
    g_sd[i * 4 + h] = su;
    g_ss[i * 4 + h] = sw;
}

// ---------------- K2: edge pass (PDL consumer) + Wc/bc build in tail blocks ----------------
__global__ __launch_bounds__(256) void k2(const int* __restrict__ ei,
                                          const float* __restrict__ x,
                                          const float* __restrict__ ea,
                                          const float* __restrict__ Wv,
                                          const float* __restrict__ bv,
                                          const float* __restrict__ We,
                                          const float* __restrict__ Wskip,
                                          const float* __restrict__ W1,
                                          const float* __restrict__ b1,
                                          const float* __restrict__ bskip) {
    if (blockIdx.x >= 1563) {
        // Wc/bc build — reads only harness inputs; consumed only by k6.
        // No cudaGridDependencySynchronize needed (independent of k1 output).
        int idx = (blockIdx.x - 1563) * 256 + threadIdx.x;
        if (idx < 7168) {
            int j = idx >> 6, c = idx & 63;
            float s = 0.f;
            if (j < 108) {
                const float* src;
                float sc = 0.25f;
                if (j < 64)      { int h = j >> 4, a = j & 15; src = Wv + a * HC + h * CC; }
                else if (j < 88) { int t = j - 64, h = t / 6, dd = t - h * 6; src = We + dd * HC + h * CC; }
                else if (j < 104){ src = Wskip + (j - 88) * CC; sc = 1.f; }
                else             { int h = j - 104; src = bv + h * CC; }
                float s0 = 0.f, s1 = 0.f, s2 = 0.f, s3 = 0.f;
                for (int k = 0; k + 4 <= CC; k += 4) {
                    s0 += src[k]     * W1[(k)     * 64 + c];
                    s1 += src[k + 1] * W1[(k + 1) * 64 + c];
                    s2 += src[k + 2] * W1[(k + 2) * 64 + c];
                    s3 += src[k + 3] * W1[(k + 3) * 64 + c];
                }
                s = ((s0 + s1) + (s2 + s3)) * sc;
            }
            g_Wc[idx] = s;
        } else if (idx < 7232) {
            int c = idx - 7168;
            float s0 = 0.f, s1 = 0.f;
            for (int k = 0; k + 2 <= CC; k += 2) {
                s0 += bskip[k]     * W1[(k)     * 64 + c];
                s1 += bskip[k + 1] * W1[(k + 1) * 64 + c];
            }
            g_bc[c] = s0 + s1 + b1[c];
        }
        return;
    }

    int gid = blockIdx.x * 256 + threadIdx.x;
    bool act = (gid < EE * 4);
    int e = gid >> 2, h = gid & 3;
    int s = 0, d = 0;
    float xs[16], eav[6];
    if (act) {
        s = __ldg(ei + e);
        d = __ldg(ei + EE + e);
        const float4* xr = (const float4*)(x + (size_t)s * 16);
#pragma unroll
        for (int t = 0; t < 4; t++) {
            float4 f = __ldg(xr + t);
            xs[4 * t + 0] = f.x; xs[4 * t + 1] = f.y; xs[4 * t + 2] = f.z; xs[4 * t + 3] = f.w;
        }
        const float2* er = (const float2*)(ea + (size_t)e * 6);
#pragma unroll
        for (int t = 0; t < 3; t++) {
            float2 f = __ldg(er + t);
            eav[2 * t] = f.x; eav[2 * t + 1] = f.y;
        }
    }

    cudaGridDependencySynchronize();   // k1 results now visible
    if (!act) return;

    float al = __ldg(g_sd + d * 4 + h) + __ldg(g_ss + s * 4 + h);
    const float4* pd = (const float4*)(g_p + d * 64 + h * 16);
#pragma unroll
    for (int t = 0; t < 4; t++) {
        float4 f = __ldg(pd + t);
        al += f.x * xs[4 * t + 0] + f.y * xs[4 * t + 1] + f.z * xs[4 * t + 2] + f.w * xs[4 * t + 3];
    }
    float4 xga = __ldg((const float4*)(g_xgp + d * 32 + h * 8));
    float2 xgb = __ldg((const float2*)(g_xgp + d * 32 + h * 8 + 4));
    al += eav[0] * xga.x + eav[1] * xga.y + eav[2] * xga.z + eav[3] * xga.w
        + eav[4] * xgb.x + eav[5] * xgb.y;
    al *= 0.05976143046671968f;  // 1/sqrt(280)
    float ex = __expf(al);

    float* Sd = g_Sp + d * 32 + h * 8;
    red4(Sd, ex * eav[0], ex * eav[1], ex * eav[2], ex * eav[3]);
    red4(Sd + 4, ex * eav[4], ex * eav[5], ex, 0.f);   // S[4],S[5],A,pad
    float* Td = g_T + d * 64 + h * 16;
#pragma unroll
    for (int t = 0; t < 4; t++)
        red4(Td + 4 * t, ex * xs[4 * t], ex * xs[4 * t + 1], ex * xs[4 * t + 2], ex * xs[4 * t + 3]);
}

// ---------------- K6: fused MLP (R12 proven; PDL consumer: weights before sync) ----------
#define FP 68
#define K6DYN ((7168 + 112 * FP) * 4)
__global__ __launch_bounds__(256) void k6(const float* __restrict__ x,
                                          const float* __restrict__ W2,
                                          const float* __restrict__ b2,
                                          const float* __restrict__ W3,
                                          const float* __restrict__ b3,
                                          float* __restrict__ out) {
    extern __shared__ float dyn[];
    float* Wcs = dyn;              // [112][64]
    float* Fs = dyn + 7168;        // [112][FP]
    float* Hs1 = dyn;              // alias of Wcs after stage 1: [64][68]
    __shared__ float invAs[256], als[256];
    __shared__ float W2s[1024], b2s[16], W3s[96], b3s[6], bcs[64];

    int tid = threadIdx.x;
    int nodeBase = blockIdx.x * 64;

    // --- prefix: harness inputs only ---
    for (int t = tid; t < 1024; t += 256) W2s[t] = W2[t];
    if (tid < 16) b2s[tid] = b2[tid];
    if (tid < 96) W3s[tid] = W3[tid];
    if (tid < 6) b3s[tid] = b3[tid];

    cudaGridDependencySynchronize();   // k2 (edge pass + Wc build) complete

    for (int t = tid; t < 7168; t += 256) Wcs[t] = g_Wc[t];
    if (tid < 64) bcs[tid] = g_bc[tid];
    {
        int n = tid >> 2;
        int node = nodeBase + n;
        float a = (node < NN) ? g_Sp[node * 32 + (tid & 3) * 8 + 6] : 0.f;
        float inv = 1.f / (a + 1e-16f);
        invAs[tid] = inv;
        als[tid] = a * inv;
    }
    __syncthreads();

    for (int idx = tid; idx < 1024; idx += 256) {          // T: 64 nodes x 16 vec4
        int n = idx >> 4, v = idx & 15;
        int node = nodeBase + n;
        float4 t4 = (node < NN) ? ((const float4*)g_T)[node * 16 + v]
                                : make_float4(0.f, 0.f, 0.f, 0.f);
        float inv = invAs[n * 4 + (v >> 2)];
        Fs[(v * 4 + 0) * FP + n] = t4.x * inv;
        Fs[(v * 4 + 1) * FP + n] = t4.y * inv;
        Fs[(v * 4 + 2) * FP + n] = t4.z * inv;
        Fs[(v * 4 + 3) * FP + n] = t4.w * inv;
    }
    for (int idx = tid; idx < 2048; idx += 256) {          // S: 64 nodes x 24 (of 32)
        int n = idx >> 5, r = idx & 31;
        if (r < 24) {
            int node = nodeBase + n;
            int h = r / 6, dd = r - h * 6;
            float v = (node < NN) ? g_Sp[node * 32 + h * 8 + dd] * invAs[n * 4 + h] : 0.f;
            Fs[(64 + r) * FP + n] = v;
        }
    }
    for (int idx = tid; idx < 1024; idx += 256) {          // x: 64 nodes x 16
        int n = idx >> 4, f = idx & 15;
        int node = nodeBase + n;
        Fs[(88 + f) * FP + n] = (node < NN) ? x[(size_t)node * 16 + f] : 0.f;
    }
    {
        int n = tid >> 2, h = tid & 3;
        Fs[(104 + h) * FP + n] = als[tid];
        Fs[(108 + h) * FP + n] = 0.f;
    }
    __syncthreads();

    // stage 1: [64 nodes] x [64 cols], K=112, 4x4 FFMA2 tile, 2-deep pipeline
    int tx = tid & 15, ty = tid >> 4;
    unsigned long long a2[2][4] = {{0ull, 0ull, 0ull, 0ull}, {0ull, 0ull, 0ull, 0ull}};
    const float* fbase = Fs + ty * 4;
    const float* wbase = Wcs + tx * 4;
    ulonglong2 fp_n = *(const ulonglong2*)(fbase);
    float4 wv_n = *(const float4*)(wbase);
#pragma unroll 4
    for (int k = 0; k < 112; k++) {
        ulonglong2 fp = fp_n;
        float4 wv = wv_n;
        if (k < 111) {
            fp_n = *(const ulonglong2*)(fbase + (k + 1) * FP);
            wv_n = *(const float4*)(wbase + (k + 1) * 64);
        }
        unsigned long long w0 = dup2(wv.x), w1 = dup2(wv.y), w2 = dup2(wv.z), w3 = dup2(wv.w);
        ffma2(a2[0][0], fp.x, w0); ffma2(a2[0][1], fp.x, w1);
        ffma2(a2[0][2], fp.x, w2); ffma2(a2[0][3], fp.x, w3);
        ffma2(a2[1][0], fp.y, w0); ffma2(a2[1][1], fp.y, w1);
        ffma2(a2[1][2], fp.y, w2); ffma2(a2[1][3], fp.y, w3);
    }
    __syncthreads();  // done reading Wcs; safe to alias as Hs1
#pragma unroll
    for (int p = 0; p < 2; p++)
#pragma unroll
        for (int j = 0; j < 4; j++) {
            float lo, hi;
            unpack2(a2[p][j], lo, hi);
            float b = bcs[tx * 4 + j];
            Hs1[(ty * 4 + 2 * p) * 68 + tx * 4 + j]     = fmaxf(lo + b, 0.f);
            Hs1[(ty * 4 + 2 * p + 1) * 68 + tx * 4 + j] = fmaxf(hi + b, 0.f);
        }
    __syncthreads();

    // stage 2+3: 4 lanes per node, packed FFMA2
    int n = tid >> 2, q = tid & 3;
    int node = nodeBase + n;
    unsigned long long h2p[2];
    h2p[0] = pack2(b2s[q * 4 + 0], b2s[q * 4 + 1]);
    h2p[1] = pack2(b2s[q * 4 + 2], b2s[q * 4 + 3]);
#pragma unroll 8
    for (int k = 0; k < 64; k++) {
        unsigned long long hd = dup2(Hs1[n * 68 + k]);
        ulonglong2 wp = *(const ulonglong2*)(W2s + k * 16 + q * 4);
        ffma2(h2p[0], hd, wp.x);
        ffma2(h2p[1], hd, wp.y);
    }
    float h2[4];
    unpack2(h2p[0], h2[0], h2[1]);
    unpack2(h2p[1], h2[2], h2[3]);
#pragma unroll
    for (int mm = 0; mm < 4; mm++) h2[mm] = fmaxf(h2[mm], 0.f);

    float lg[6];
#pragma unroll
    for (int o = 0; o < 6; o++) {
        float pz = 0.f;
#pragma unroll
        for (int mm = 0; mm < 4; mm++) pz += h2[mm] * W3s[(q * 4 + mm) * 6 + o];
        lg[o] = pz;
    }
#pragma unroll
    for (int o = 0; o < 6; o++) {
        lg[o] += __shfl_xor_sync(0xffffffffu, lg[o], 1);
        lg[o] += __shfl_xor_sync(0xffffffffu, lg[o], 2);
        lg[o] += b3s[o];
    }
    float mx = lg[0];
#pragma unroll
    for (int o = 1; o < 6; o++) mx = fmaxf(mx, lg[o]);
    float ev[6], sum = 0.f;
#pragma unroll
    for (int o = 0; o < 6; o++) { ev[o] = __expf(lg[o] - mx); sum += ev[o]; }
    float inv = 1.f / sum;
    if (q == 0 && node < NN) {
#pragma unroll
        for (int o = 0; o < 6; o++) out[node * 6 + o] = ev[o] * inv;
    }
}

// ---------------- launch (PDL chaining) ----------------
template <typename... Args>
static void launch_pdl(void (*kern)(Args...), dim3 grid, dim3 block, size_t smem, Args... args) {
    cudaLaunchConfig_t cfg = {};
    cfg.gridDim = grid;
    cfg.blockDim = block;
    cfg.dynamicSmemBytes = smem;
    cfg.stream = 0;
    cudaLaunchAttribute attr[1];
    attr[0].id = cudaLaunchAttributeProgrammaticStreamSerialization;
    attr[0].val.programmaticStreamSerializationAllowed = 1;
    cfg.attrs = attr;
    cfg.numAttrs = 1;
    cudaLaunchKernelEx(&cfg, kern, args...);
}

extern "C" void kernel_launch(void* const* d_in, const int* in_sizes, int n_in,
                              void* d_out, int out_size) {
    const float* x      = (const float*)d_in[0];
    const int* ei       = (const int*)d_in[1];
    const float* ea     = (const float*)d_in[2];
    const float* Wq     = (const float*)d_in[3];
    const float* bq     = (const float*)d_in[4];
    const float* Wk     = (const float*)d_in[5];
    const float* bk     = (const float*)d_in[6];
    const float* Wv     = (const float*)d_in[7];
    const float* bv     = (const float*)d_in[8];
    const float* We     = (const float*)d_in[9];
    const float* Wskip  = (const float*)d_in[10];
    const float* bskip  = (const float*)d_in[11];
    const float* W1     = (const float*)d_in[12];
    const float* b1     = (const float*)d_in[13];
    const float* W2     = (const float*)d_in[14];
    const float* b2     = (const float*)d_in[15];
    const float* W3     = (const float*)d_in[16];
    const float* b3     = (const float*)d_in[17];
    float* out = (float*)d_out;

    cudaFuncSetAttribute(k6, cudaFuncAttributeMaxDynamicSharedMemorySize, K6DYN);

    kA<<<196, 256>>>(Wq, bq, Wk, bk, We);
    launch_pdl(k1, dim3(391), dim3(256), (size_t)0, x);
    launch_pdl(k2, dim3(1592), dim3(256), (size_t)0, ei, x, ea, Wv, bv, We, Wskip, W1, b1, bskip);
    launch_pdl(k6, dim3(391), dim3(256), (size_t)K6DYN, x, W2, b2, W3, b3, out);
}

// round 17
// speedup vs baseline: 1.2281x; 1.1326x over previous
#include <cuda_runtime.h>

#define NN 25000
#define EE 100000
#define NH 4
#define CC 280
#define HC 1120

// ---------------- scratch ----------------
__device__ __align__(16) float g_M[NH * 256];
__device__ __align__(16) float g_G[NH * 6 * 16];
__device__ __align__(16) float g_g0[NH * 6];
__device__ __align__(16) float g_u[NH * 16];
__device__ __align__(16) float g_w[NH * 16];
__device__ __align__(16) float g_c0[NH];

__device__ __align__(16) float g_p[NN * 64];     // x_i @ M_h  [N][H][16]
__device__ __align__(16) float g_xgp[NN * 32];   // [N][H][8] (6 used)
__device__ __align__(16) float g_sd[NN * 4];
__device__ __align__(16) float g_ss[NN * 4];

__device__ __align__(16) float g_T[NN * 64];     // sum ex*x[src]  [N][H][16]
__device__ __align__(16) float g_Sp[NN * 32];    // [N][H][8]: S[0..5], A at [6]

__device__ __align__(16) float g_Wc[112 * 64];   // combined (W108 @ W1)
__device__ __align__(16) float g_bc[64];         // b1 + bskip @ W1

__device__ __forceinline__ float wsum(float s) {
    s += __shfl_xor_sync(0xffffffffu, s, 16);
    s += __shfl_xor_sync(0xffffffffu, s, 8);
    s += __shfl_xor_sync(0xffffffffu, s, 4);
    s += __shfl_xor_sync(0xffffffffu, s, 2);
    s += __shfl_xor_sync(0xffffffffu, s, 1);
    return s;
}

__device__ __forceinline__ void red4(float* p, float a, float b, float c, float d) {
    asm volatile("red.global.add.v4.f32 [%0], {%1,%2,%3,%4};"
                 :: "l"(__cvta_generic_to_global(p)), "f"(a), "f"(b), "f"(c), "f"(d) : "memory");
}
// packed f32x2 ops (sm_103a, PTX-only)
__device__ __forceinline__ void ffma2(unsigned long long& acc, unsigned long long a, unsigned long long b) {
    asm("fma.rn.f32x2 %0, %1, %2, %0;" : "+l"(acc) : "l"(a), "l"(b));
}
__device__ __forceinline__ unsigned long long dup2(float v) {
    unsigned long long r;
    asm("mov.b64 %0, {%1, %1};" : "=l"(r) : "f"(v));
    return r;
}
__device__ __forceinline__ unsigned long long pack2(float lo, float hi) {
    unsigned long long r;
    asm("mov.b64 %0, {%1, %2};" : "=l"(r) : "f"(lo), "f"(hi));
    return r;
}
__device__ __forceinline__ void unpack2(unsigned long long v, float& lo, float& hi) {
    asm("mov.b64 {%0, %1}, %2;" : "=f"(lo), "=f"(hi) : "l"(v));
}

// ---------------- kA: tiny weight contractions only (196 blocks) ----------------
__global__ __launch_bounds__(256) void kA(const float* __restrict__ Wq, const float* __restrict__ bq,
                                          const float* __restrict__ Wk, const float* __restrict__ bk,
                                          const float* __restrict__ We) {
    int g = blockIdx.x * 8 + (threadIdx.x >> 5);
    int lane = threadIdx.x & 31;
    if (g >= 1564) return;
    const float *pa, *pb;
    float* op;
    if (g < 1024) {
        int h = g >> 8, a = (g >> 4) & 15, b = g & 15;
        pa = Wq + a * HC + h * CC; pb = Wk + b * HC + h * CC; op = &g_M[g];
    } else if (g < 1408) {
        int t = g - 1024, h = t / 96, r = t % 96, dd = r >> 4, a = r & 15;
        pa = Wq + a * HC + h * CC; pb = We + dd * HC + h * CC; op = &g_G[(h * 6 + dd) * 16 + a];
    } else if (g < 1472) {
        int t = g - 1408, h = t >> 4, a = t & 15;
        pa = Wq + a * HC + h * CC; pb = bk + h * CC; op = &g_u[t];
    } else if (g < 1536) {
        int t = g - 1472, h = t >> 4, a = t & 15;
        pa = Wk + a * HC + h * CC; pb = bq + h * CC; op = &g_w[t];
    } else if (g < 1540) {
        int h = g - 1536;
        pa = bq + h * CC; pb = bk + h * CC; op = &g_c0[h];
    } else {
        int t = g - 1540, h = t / 6, dd = t - h * 6;
        pa = bq + h * CC; pb = We + dd * HC + h * CC; op = &g_g0[t];
    }
    float s = 0.f;
    for (int c = lane; c < CC; c += 32) s += pa[c] * pb[c];
    s = wsum(s);
    if (lane == 0) *op = s;
}

// ---------------- K1: node precompute (blocks 0..390, PDL consumer)
//                  + Wc/bc build (blocks 391..420, harness inputs only) ----------------
__global__ __launch_bounds__(256) void k1(const float* __restrict__ x,
                                          const float* __restrict__ Wv,
                                          const float* __restrict__ bv,
                                          const float* __restrict__ We,
                                          const float* __restrict__ Wskip,
                                          const float* __restrict__ W1,
                                          const float* __restrict__ b1,
                                          const float* __restrict__ bskip) {
    if (blockIdx.x >= 391) {
        // Wc/bc build — reads only harness inputs; consumed only by k6
        // (k6 syncs on k2, which synced on k1 → visibility guaranteed).
        int idx = (blockIdx.x - 391) * 256 + threadIdx.x;
        if (idx < 7168) {
            int j = idx >> 6, c = idx & 63;
            float s = 0.f;
            if (j < 108) {
                const float* src;
                float sc = 0.25f;
                if (j < 64)      { int h = j >> 4, a = j & 15; src = Wv + a * HC + h * CC; }
                else if (j < 88) { int t = j - 64, h = t / 6, dd = t - h * 6; src = We + dd * HC + h * CC; }
                else if (j < 104){ src = Wskip + (j - 88) * CC; sc = 1.f; }
                else             { int h = j - 104; src = bv + h * CC; }
                float s0 = 0.f, s1 = 0.f, s2 = 0.f, s3 = 0.f;
                for (int k = 0; k + 4 <= CC; k += 4) {
                    s0 += src[k]     * W1[(k)     * 64 + c];
                    s1 += src[k + 1] * W1[(k + 1) * 64 + c];
                    s2 += src[k + 2] * W1[(k + 2) * 64 + c];
                    s3 += src[k + 3] * W1[(k + 3) * 64 + c];
                }
                s = ((s0 + s1) + (s2 + s3)) * sc;
            }
            g_Wc[idx] = s;
        } else if (idx < 7232) {
            int c = idx - 7168;
            float s0 = 0.f, s1 = 0.f;
            for (int k = 0; k + 2 <= CC; k += 2) {
                s0 += bskip[k]     * W1[(k)     * 64 + c];
                s1 += bskip[k + 1] * W1[(k + 1) * 64 + c];
            }
            g_bc[c] = s0 + s1 + b1[c];
        }
        return;
    }

    __shared__ float sM[NH * 256];
    __shared__ float sG[NH * 96];
    __shared__ float sU[NH * 16];
    __shared__ float sW[NH * 16];
    __shared__ float sC0[NH];
    __shared__ float sG0[NH * 6];

    // --- prefix: load x (harness input, no dependency on kA) ---
    int gid = blockIdx.x * 256 + threadIdx.x;
    int i = gid >> 2, h = gid & 3;
    float xv[16];
    bool act = (i < NN);
    if (act) {
        const float4* xr = (const float4*)(x + (size_t)i * 16);
#pragma unroll
        for (int t = 0; t < 4; t++) {
            float4 f = xr[t];
            xv[4 * t + 0] = f.x; xv[4 * t + 1] = f.y; xv[4 * t + 2] = f.z; xv[4 * t + 3] = f.w;
        }
    }

    cudaGridDependencySynchronize();   // kA results now visible

    for (int t = threadIdx.x; t < NH * 256; t += 256) sM[t] = g_M[t];
    if (threadIdx.x < NH * 96) sG[threadIdx.x] = g_G[threadIdx.x];
    if (threadIdx.x < NH * 16) { sU[threadIdx.x] = g_u[threadIdx.x]; sW[threadIdx.x] = g_w[threadIdx.x]; }
    if (threadIdx.x < NH) sC0[threadIdx.x] = g_c0[threadIdx.x];
    if (threadIdx.x < NH * 6) sG0[threadIdx.x] = g_g0[threadIdx.x];
    __syncthreads();

    if (!act) return;
    const float4 z4 = make_float4(0.f, 0.f, 0.f, 0.f);
    float4* po = (float4*)(g_p + i * 64 + h * 16);
    float4* to = (float4*)(g_T + i * 64 + h * 16);
#pragma unroll
    for (int t = 0; t < 4; t++) {
        float pv[4];
#pragma unroll
        for (int j = 0; j < 4; j++) {
            int b = t * 4 + j;
            float s = 0.f;
#pragma unroll
            for (int a = 0; a < 16; a++) s += xv[a] * sM[(h * 16 + a) * 16 + b];
            pv[j] = s;
        }
        po[t] = make_float4(pv[0], pv[1], pv[2], pv[3]);
        to[t] = z4;
    }
    float xg[6];
#pragma unroll
    for (int dd = 0; dd < 6; dd++) {
        float s = sG0[h * 6 + dd];
#pragma unroll
        for (int a = 0; a < 16; a++) s += xv[a] * sG[(h * 6 + dd) * 16 + a];
        xg[dd] = s;
    }
    float4* xo = (float4*)(g_xgp + i * 32 + h * 8);
    xo[0] = make_float4(xg[0], xg[1], xg[2], xg[3]);
    *(float2*)(g_xgp + i * 32 + h * 8 + 4) = make_float2(xg[4], xg[5]);
    float4* so = (float4*)(g_Sp + i * 32 + h * 8);
    so[0] = z4; so[1] = z4;   // zeros S[0..5] and A slot [6]

    float su = sC0[h], sw = 0.f;
#pragma unroll
    for (int a = 0; a < 16; a++) {
        su += xv[a] * sU[h * 16 + a];
        sw += xv[a] * sW[h * 16 + a];
    }
    g_sd[i * 4 + h] = su;
    g_ss[i * 4 + h] = sw;
}

// ---------------- K2: edge pass (PDL consumer: gather inputs before sync) ----------------
__global__ __launch_bounds__(256) void k2(const int* __restrict__ ei,
                                          const float* __restrict__ x,
                                          const float* __restrict__ ea) {
    int gid = blockIdx.x * 256 + threadIdx.x;
    bool act = (gid < EE * 4);
    int e = gid >> 2, h = gid & 3;
    int s = 0, d = 0;
    float xs[16], eav[6];
    if (act) {
        s = __ldg(ei + e);
        d = __ldg(ei + EE + e);
        const float4* xr = (const float4*)(x + (size_t)s * 16);
#pragma unroll
        for (int t = 0; t < 4; t++) {
            float4 f = __ldg(xr + t);
            xs[4 * t + 0] = f.x; xs[4 * t + 1] = f.y; xs[4 * t + 2] = f.z; xs[4 * t + 3] = f.w;
        }
        const float2* er = (const float2*)(ea + (size_t)e * 6);
#pragma unroll
        for (int t = 0; t < 3; t++) {
            float2 f = __ldg(er + t);
            eav[2 * t] = f.x; eav[2 * t + 1] = f.y;
        }
    }

    cudaGridDependencySynchronize();   // k1 results now visible
    if (!act) return;

    float al = __ldg(g_sd + d * 4 + h) + __ldg(g_ss + s * 4 + h);
    const float4* pd = (const float4*)(g_p + d * 64 + h * 16);
#pragma unroll
    for (int t = 0; t < 4; t++) {
        float4 f = __ldg(pd + t);
        al += f.x * xs[4 * t + 0] + f.y * xs[4 * t + 1] + f.z * xs[4 * t + 2] + f.w * xs[4 * t + 3];
    }
    float4 xga = __ldg((const float4*)(g_xgp + d * 32 + h * 8));
    float2 xgb = __ldg((const float2*)(g_xgp + d * 32 + h * 8 + 4));
    al += eav[0] * xga.x + eav[1] * xga.y + eav[2] * xga.z + eav[3] * xga.w
        + eav[4] * xgb.x + eav[5] * xgb.y;
    al *= 0.05976143046671968f;  // 1/sqrt(280)
    float ex = __expf(al);

    float* Sd = g_Sp + d * 32 + h * 8;
    red4(Sd, ex * eav[0], ex * eav[1], ex * eav[2], ex * eav[3]);
    red4(Sd + 4, ex * eav[4], ex * eav[5], ex, 0.f);   // S[4],S[5],A,pad
    float* Td = g_T + d * 64 + h * 16;
#pragma unroll
    for (int t = 0; t < 4; t++)
        red4(Td + 4 * t, ex * xs[4 * t], ex * xs[4 * t + 1], ex * xs[4 * t + 2], ex * xs[4 * t + 3]);
}

// ---------------- K6: fused MLP (R12 proven; PDL consumer: weights before sync) ----------
#define FP 68
#define K6DYN ((7168 + 112 * FP) * 4)
__global__ __launch_bounds__(256) void k6(const float* __restrict__ x,
                                          const float* __restrict__ W2,
                                          const float* __restrict__ b2,
                                          const float* __restrict__ W3,
                                          const float* __restrict__ b3,
                                          float* __restrict__ out) {
    extern __shared__ float dyn[];
    float* Wcs = dyn;              // [112][64]
    float* Fs = dyn + 7168;        // [112][FP]
    float* Hs1 = dyn;              // alias of Wcs after stage 1: [64][68]
    __shared__ float invAs[256], als[256];
    __shared__ float W2s[1024], b2s[16], W3s[96], b3s[6], bcs[64];

    int tid = threadIdx.x;
    int nodeBase = blockIdx.x * 64;

    // --- prefix: harness inputs only ---
    for (int t = tid; t < 1024; t += 256) W2s[t] = W2[t];
    if (tid < 16) b2s[tid] = b2[tid];
    if (tid < 96) W3s[tid] = W3[tid];
    if (tid < 6) b3s[tid] = b3[tid];

    cudaGridDependencySynchronize();   // k2 complete ⇒ k1 complete ⇒ g_Wc/g_bc ready

    for (int t = tid; t < 7168; t += 256) Wcs[t] = g_Wc[t];
    if (tid < 64) bcs[tid] = g_bc[tid];
    {
        int n = tid >> 2;
        int node = nodeBase + n;
        float a = (node < NN) ? g_Sp[node * 32 + (tid & 3) * 8 + 6] : 0.f;
        float inv = 1.f / (a + 1e-16f);
        invAs[tid] = inv;
        als[tid] = a * inv;
    }
    __syncthreads();

    for (int idx = tid; idx < 1024; idx += 256) {          // T: 64 nodes x 16 vec4
        int n = idx >> 4, v = idx & 15;
        int node = nodeBase + n;
        float4 t4 = (node < NN) ? ((const float4*)g_T)[node * 16 + v]
                                : make_float4(0.f, 0.f, 0.f, 0.f);
        float inv = invAs[n * 4 + (v >> 2)];
        Fs[(v * 4 + 0) * FP + n] = t4.x * inv;
        Fs[(v * 4 + 1) * FP + n] = t4.y * inv;
        Fs[(v * 4 + 2) * FP + n] = t4.z * inv;
        Fs[(v * 4 + 3) * FP + n] = t4.w * inv;
    }
    for (int idx = tid; idx < 2048; idx += 256) {          // S: 64 nodes x 24 (of 32)
        int n = idx >> 5, r = idx & 31;
        if (r < 24) {
            int node = nodeBase + n;
            int h = r / 6, dd = r - h * 6;
            float v = (node < NN) ? g_Sp[node * 32 + h * 8 + dd] * invAs[n * 4 + h] : 0.f;
            Fs[(64 + r) * FP + n] = v;
        }
    }
    for (int idx = tid; idx < 1024; idx += 256) {          // x: 64 nodes x 16
        int n = idx >> 4, f = idx & 15;
        int node = nodeBase + n;
        Fs[(88 + f) * FP + n] = (node < NN) ? x[(size_t)node * 16 + f] : 0.f;
    }
    {
        int n = tid >> 2, h = tid & 3;
        Fs[(104 + h) * FP + n] = als[tid];
        Fs[(108 + h) * FP + n] = 0.f;
    }
    __syncthreads();

    // stage 1: [64 nodes] x [64 cols], K=112, 4x4 FFMA2 tile, 2-deep pipeline
    int tx = tid & 15, ty = tid >> 4;
    unsigned long long a2[2][4] = {{0ull, 0ull, 0ull, 0ull}, {0ull, 0ull, 0ull, 0ull}};
    const float* fbase = Fs + ty * 4;
    const float* wbase = Wcs + tx * 4;
    ulonglong2 fp_n = *(const ulonglong2*)(fbase);
    float4 wv_n = *(const float4*)(wbase);
#pragma unroll 4
    for (int k = 0; k < 112; k++) {
        ulonglong2 fp = fp_n;
        float4 wv = wv_n;
        if (k < 111) {
            fp_n = *(const ulonglong2*)(fbase + (k + 1) * FP);
            wv_n = *(const float4*)(wbase + (k + 1) * 64);
        }
        unsigned long long w0 = dup2(wv.x), w1 = dup2(wv.y), w2 = dup2(wv.z), w3 = dup2(wv.w);
        ffma2(a2[0][0], fp.x, w0); ffma2(a2[0][1], fp.x, w1);
        ffma2(a2[0][2], fp.x, w2); ffma2(a2[0][3], fp.x, w3);
        ffma2(a2[1][0], fp.y, w0); ffma2(a2[1][1], fp.y, w1);
        ffma2(a2[1][2], fp.y, w2); ffma2(a2[1][3], fp.y, w3);
    }
    __syncthreads();  // done reading Wcs; safe to alias as Hs1
#pragma unroll
    for (int p = 0; p < 2; p++)
#pragma unroll
        for (int j = 0; j < 4; j++) {
            float lo, hi;
            unpack2(a2[p][j], lo, hi);
            float b = bcs[tx * 4 + j];
            Hs1[(ty * 4 + 2 * p) * 68 + tx * 4 + j]     = fmaxf(lo + b, 0.f);
            Hs1[(ty * 4 + 2 * p + 1) * 68 + tx * 4 + j] = fmaxf(hi + b, 0.f);
        }
    __syncthreads();

    // stage 2+3: 4 lanes per node, packed FFMA2
    int n = tid >> 2, q = tid & 3;
    int node = nodeBase + n;
    unsigned long long h2p[2];
    h2p[0] = pack2(b2s[q * 4 + 0], b2s[q * 4 + 1]);
    h2p[1] = pack2(b2s[q * 4 + 2], b2s[q * 4 + 3]);
#pragma unroll 8
    for (int k = 0; k < 64; k++) {
        unsigned long long hd = dup2(Hs1[n * 68 + k]);
        ulonglong2 wp = *(const ulonglong2*)(W2s + k * 16 + q * 4);
        ffma2(h2p[0], hd, wp.x);
        ffma2(h2p[1], hd, wp.y);
    }
    float h2[4];
    unpack2(h2p[0], h2[0], h2[1]);
    unpack2(h2p[1], h2[2], h2[3]);
#pragma unroll
    for (int mm = 0; mm < 4; mm++) h2[mm] = fmaxf(h2[mm], 0.f);

    float lg[6];
#pragma unroll
    for (int o = 0; o < 6; o++) {
        float pz = 0.f;
#pragma unroll
        for (int mm = 0; mm < 4; mm++) pz += h2[mm] * W3s[(q * 4 + mm) * 6 + o];
        lg[o] = pz;
    }
#pragma unroll
    for (int o = 0; o < 6; o++) {
        lg[o] += __shfl_xor_sync(0xffffffffu, lg[o], 1);
        lg[o] += __shfl_xor_sync(0xffffffffu, lg[o], 2);
        lg[o] += b3s[o];
    }
    float mx = lg[0];
#pragma unroll
    for (int o = 1; o < 6; o++) mx = fmaxf(mx, lg[o]);
    float ev[6], sum = 0.f;
#pragma unroll
    for (int o = 0; o < 6; o++) { ev[o] = __expf(lg[o] - mx); sum += ev[o]; }
    float inv = 1.f / sum;
    if (q == 0 && node < NN) {
#pragma unroll
        for (int o = 0; o < 6; o++) out[node * 6 + o] = ev[o] * inv;
    }
}

// ---------------- launch (PDL chaining) ----------------
template <typename... Args>
static void launch_pdl(void (*kern)(Args...), dim3 grid, dim3 block, size_t smem, Args... args) {
    cudaLaunchConfig_t cfg = {};
    cfg.gridDim = grid;
    cfg.blockDim = block;
    cfg.dynamicSmemBytes = smem;
    cfg.stream = 0;
    cudaLaunchAttribute attr[1];
    attr[0].id = cudaLaunchAttributeProgrammaticStreamSerialization;
    attr[0].val.programmaticStreamSerializationAllowed = 1;
    cfg.attrs = attr;
    cfg.numAttrs = 1;
    cudaLaunchKernelEx(&cfg, kern, args...);
}

extern "C" void kernel_launch(void* const* d_in, const int* in_sizes, int n_in,
                              void* d_out, int out_size) {
    const float* x      = (const float*)d_in[0];
    const int* ei       = (const int*)d_in[1];
    const float* ea     = (const float*)d_in[2];
    const float* Wq     = (const float*)d_in[3];
    const float* bq     = (const float*)d_in[4];
    const float* Wk     = (const float*)d_in[5];
    const float* bk     = (const float*)d_in[6];
    const float* Wv     = (const float*)d_in[7];
    const float* bv     = (const float*)d_in[8];
    const float* We     = (const float*)d_in[9];
    const float* Wskip  = (const float*)d_in[10];
    const float* bskip  = (const float*)d_in[11];
    const float* W1     = (const float*)d_in[12];
    const float* b1     = (const float*)d_in[13];
    const float* W2     = (const float*)d_in[14];
    const float* b2     = (const float*)d_in[15];
    const float* W3     = (const float*)d_in[16];
    const float* b3     = (const float*)d_in[17];
    float* out = (float*)d_out;

    cudaFuncSetAttribute(k6, cudaFuncAttributeMaxDynamicSharedMemorySize, K6DYN);

    kA<<<196, 256>>>(Wq, bq, Wk, bk, We);
    launch_pdl(k1, dim3(421), dim3(256), (size_t)0, x, Wv, bv, We, Wskip, W1, b1, bskip);
    launch_pdl(k2, dim3(1563), dim3(256), (size_t)0, ei, x, ea);
    launch_pdl(k6, dim3(391), dim3(256), (size_t)K6DYN, x, W2, b2, W3, b3, out);
}